// round 6
// baseline (speedup 1.0000x reference)
#include <cuda_runtime.h>
#include <math.h>

#define Nn   50000
#define Ee   800000
#define E2c  850000      // E + N self-loops
#define NG   64
#define NCLS 10

// ---------------- device scratch (no allocations allowed) ----------------
__device__ float g_h[(size_t)Nn * 128];     // per-layer GEMM output  [N,128]
__device__ float g_out[(size_t)Nn * 128];   // per-layer aggregation  [N,128]
__device__ float g_p[(size_t)E2c * 2];      // edge logits -> probs   [E2,H]
__device__ int   g_menc[Nn * 2];            // encoded segment max    [N,H]
__device__ float g_z[Nn * 2];               // segment sum            [N,H]
__device__ float g_asrc[Nn * 2];            // alpha_src              [N,H]
__device__ float g_adst[Nn * 2];            // alpha_dst              [N,H]
__device__ float g_pool[NG * 128];
__device__ float g_cnt[NG];
__device__ int   g_is64;                    // 1 if indices are int64

// ---------------- helpers ----------------
__device__ __forceinline__ float eluf(float v) { return v > 0.f ? v : expm1f(v); }
// monotonic float->int encoding for atomicMax over floats (incl. negatives)
__device__ __forceinline__ int encf(float f) {
    int i = __float_as_int(f);
    return i >= 0 ? i : (i ^ 0x7FFFFFFF);
}
__device__ __forceinline__ float decf(int i) {
    return __int_as_float(i >= 0 ? i : (i ^ 0x7FFFFFFF));
}
__device__ __forceinline__ int loadIdx(const void* p, int i) {
    if (g_is64) return (int)((const long long*)p)[i];
    return ((const int*)p)[i];
}
__device__ __forceinline__ void red_add_v4(float* dst, float4 v) {
    asm volatile("red.global.add.v4.f32 [%0], {%1,%2,%3,%4};"
                 :: "l"(dst), "f"(v.x), "f"(v.y), "f"(v.z), "f"(v.w) : "memory");
}

// ---------------- dtype detection (int32 vs int64 edge indices) ----------------
__global__ void detect_kernel(const int* ei32) {
    __shared__ int sh;
    if (threadIdx.x == 0) sh = 0;
    __syncthreads();
    int v = 0;
    for (int i = threadIdx.x; i < 2048; i += 256) v |= ei32[2 * i + 1];
    atomicOr(&sh, v);
    __syncthreads();
    if (threadIdx.x == 0) g_is64 = (sh == 0) ? 1 : 0;
}

// ---------------- GEMM: g_h = act(X) @ W  (128x128 tile, BK=16) ----------------
// MODE 0: X = raw input.  MODE 1: X = elu(g_out + biasPrev)  (previous layer act)
template <int MODE>
__global__ void gemm_kernel(const float* __restrict__ X,
                            const float* __restrict__ Wm,
                            const float* __restrict__ biasPrev) {
    __shared__ float As[16][128];   // [k][m]
    __shared__ float Bs[16][128];   // [k][n]
    const int tid = threadIdx.x;
    const int bm  = blockIdx.x * 128;
    const int tx  = tid & 15;       // 16 col-groups of 8
    const int ty  = tid >> 4;       // 16 row-groups of 8
    float acc[8][8];
#pragma unroll
    for (int i = 0; i < 8; i++)
#pragma unroll
        for (int j = 0; j < 8; j++) acc[i][j] = 0.f;

    for (int k0 = 0; k0 < 128; k0 += 16) {
#pragma unroll
        for (int t = 0; t < 2; t++) {
            int e   = tid + t * 256;        // float4 index 0..511
            // A tile: rows bm..bm+127, cols k0..k0+15
            int row = e >> 2;
            int kk4 = (e & 3) << 2;
            int gr  = bm + row;
            float4 v = make_float4(0.f, 0.f, 0.f, 0.f);
            if (gr < Nn) {
                if (MODE == 0) {
                    v = *(const float4*)(X + (size_t)gr * 128 + k0 + kk4);
                } else {
                    v = *(const float4*)(g_out + (size_t)gr * 128 + k0 + kk4);
                    v.x = eluf(v.x + biasPrev[k0 + kk4 + 0]);
                    v.y = eluf(v.y + biasPrev[k0 + kk4 + 1]);
                    v.z = eluf(v.z + biasPrev[k0 + kk4 + 2]);
                    v.w = eluf(v.w + biasPrev[k0 + kk4 + 3]);
                }
            }
            As[kk4 + 0][row] = v.x;
            As[kk4 + 1][row] = v.y;
            As[kk4 + 2][row] = v.z;
            As[kk4 + 3][row] = v.w;
            // B tile: W rows k0..k0+15, all 128 cols
            int kb = e >> 5;
            int n4 = (e & 31) << 2;
            *(float4*)&Bs[kb][n4] = *(const float4*)(Wm + (size_t)(k0 + kb) * 128 + n4);
        }
        __syncthreads();
#pragma unroll
        for (int kk = 0; kk < 16; kk++) {
            float a[8], b[8];
            *(float4*)&a[0] = *(const float4*)&As[kk][ty * 8];
            *(float4*)&a[4] = *(const float4*)&As[kk][ty * 8 + 4];
            *(float4*)&b[0] = *(const float4*)&Bs[kk][tx * 8];
            *(float4*)&b[4] = *(const float4*)&Bs[kk][tx * 8 + 4];
#pragma unroll
            for (int i = 0; i < 8; i++)
#pragma unroll
                for (int j = 0; j < 8; j++)
                    acc[i][j] = fmaf(a[i], b[j], acc[i][j]);
        }
        __syncthreads();
    }
#pragma unroll
    for (int i = 0; i < 8; i++) {
        int gr = bm + ty * 8 + i;
        if (gr < Nn) {
            *(float4*)(g_h + (size_t)gr * 128 + tx * 8) =
                make_float4(acc[i][0], acc[i][1], acc[i][2], acc[i][3]);
            *(float4*)(g_h + (size_t)gr * 128 + tx * 8 + 4) =
                make_float4(acc[i][4], acc[i][5], acc[i][6], acc[i][7]);
        }
    }
}

// ---------------- per-node attention coefficients (warp per node) ----------------
__global__ void alpha_kernel(const float* __restrict__ asrc,
                             const float* __restrict__ adst) {
    int gid  = blockIdx.x * blockDim.x + threadIdx.x;
    int n    = gid >> 5;
    int lane = gid & 31;
    if (n >= Nn) return;
    float4 hv = *(const float4*)(g_h + (size_t)n * 128 + lane * 4);
    float4 a1 = ((const float4*)asrc)[lane];
    float4 a2 = ((const float4*)adst)[lane];
    float s = hv.x * a1.x + hv.y * a1.y + hv.z * a1.z + hv.w * a1.w;
    float d = hv.x * a2.x + hv.y * a2.y + hv.z * a2.z + hv.w * a2.w;
#pragma unroll
    for (int o = 8; o; o >>= 1) {
        s += __shfl_xor_sync(0xFFFFFFFFu, s, o);
        d += __shfl_xor_sync(0xFFFFFFFFu, d, o);
    }
    if ((lane & 15) == 0) {
        int head = lane >> 4;
        g_asrc[n * 2 + head] = s;
        g_adst[n * 2 + head] = d;
    }
}

// ---------------- per-layer state reset ----------------
__global__ void init_layer_kernel() {
    int i = blockIdx.x * blockDim.x + threadIdx.x;
    if (i < Nn * 128) g_out[i] = 0.f;
    if (i < Nn * 2) {
        g_menc[i] = (int)0x80000000;   // decodes to ~ -FLT_MAX side (== -inf init)
        g_z[i]    = 0.f;
    }
}

// ---------------- edge pass 1: logits + segment max ----------------
__global__ void edge_max_kernel(const void* __restrict__ ei) {
    int e = blockIdx.x * blockDim.x + threadIdx.x;
    if (e >= E2c) return;
    int s, d;
    if (e < Ee) { s = loadIdx(ei, e); d = loadIdx(ei, Ee + e); }
    else        { s = e - Ee; d = s; }
    float e0 = g_asrc[s * 2 + 0] + g_adst[d * 2 + 0];
    float e1 = g_asrc[s * 2 + 1] + g_adst[d * 2 + 1];
    e0 = e0 > 0.f ? e0 : 0.2f * e0;   // leaky_relu 0.2
    e1 = e1 > 0.f ? e1 : 0.2f * e1;
    g_p[e * 2 + 0] = e0;
    g_p[e * 2 + 1] = e1;
    atomicMax(&g_menc[d * 2 + 0], encf(e0));
    atomicMax(&g_menc[d * 2 + 1], encf(e1));
}

// ---------------- edge pass 2: exp + segment sum ----------------
__global__ void edge_exp_kernel(const void* __restrict__ ei) {
    int e = blockIdx.x * blockDim.x + threadIdx.x;
    if (e >= E2c) return;
    int d = (e < Ee) ? loadIdx(ei, Ee + e) : (e - Ee);
    float m0 = decf(g_menc[d * 2 + 0]);
    float m1 = decf(g_menc[d * 2 + 1]);
    float p0 = __expf(g_p[e * 2 + 0] - m0);
    float p1 = __expf(g_p[e * 2 + 1] - m1);
    g_p[e * 2 + 0] = p0;
    g_p[e * 2 + 1] = p1;
    atomicAdd(&g_z[d * 2 + 0], p0);
    atomicAdd(&g_z[d * 2 + 1], p1);
}

// ---------------- edge pass 3: weighted scatter (warp per edge) ----------------
__global__ void scatter_kernel(const void* __restrict__ ei) {
    int gid = blockIdx.x * blockDim.x + threadIdx.x;
    int e   = gid >> 5;
    if (e >= E2c) return;
    int lane = gid & 31;
    int s, d;
    if (e < Ee) { s = loadIdx(ei, e); d = loadIdx(ei, Ee + e); }
    else        { s = e - Ee; d = s; }
    int hh  = lane >> 4;                          // lanes 0-15 head0, 16-31 head1
    float a = g_p[e * 2 + hh] / g_z[d * 2 + hh];
    float4 hv = *(const float4*)(g_h + (size_t)s * 128 + lane * 4);
    hv.x *= a; hv.y *= a; hv.z *= a; hv.w *= a;
    red_add_v4(g_out + (size_t)d * 128 + lane * 4, hv);
}

// ---------------- pooling ----------------
__global__ void init_pool_kernel() {
    int i = blockIdx.x * blockDim.x + threadIdx.x;
    if (i < NG * 128) g_pool[i] = 0.f;
    if (i < NG) g_cnt[i] = 0.f;
}

__global__ void pool_kernel(const void* __restrict__ batch,
                            const float* __restrict__ bias2) {
    int gid  = blockIdx.x * blockDim.x + threadIdx.x;
    int n    = gid >> 5;
    int lane = gid & 31;
    if (n >= Nn) return;
    int g = loadIdx(batch, n);
    float4 v = *(const float4*)(g_out + (size_t)n * 128 + lane * 4);
    const float* bp = bias2 + lane * 4;
    v.x = eluf(v.x + bp[0]);
    v.y = eluf(v.y + bp[1]);
    v.z = eluf(v.z + bp[2]);
    v.w = eluf(v.w + bp[3]);
    red_add_v4(g_pool + g * 128 + lane * 4, v);
    if (lane == 0) atomicAdd(&g_cnt[g], 1.0f);
}

// ---------------- classifier head + softmax ----------------
__global__ void head_kernel(const float* __restrict__ lw,
                            const float* __restrict__ lb,
                            float* __restrict__ out) {
    int g = threadIdx.x;
    if (g >= NG) return;
    float inv = 1.0f / fmaxf(g_cnt[g], 1.0f);
    float lg[NCLS];
#pragma unroll
    for (int c = 0; c < NCLS; c++) lg[c] = lb[c];
    for (int k = 0; k < 128; k++) {
        float pv = g_pool[g * 128 + k] * inv;
#pragma unroll
        for (int c = 0; c < NCLS; c++) lg[c] = fmaf(pv, lw[k * NCLS + c], lg[c]);
    }
    float mx = lg[0];
#pragma unroll
    for (int c = 1; c < NCLS; c++) mx = fmaxf(mx, lg[c]);
    float ssum = 0.f;
#pragma unroll
    for (int c = 0; c < NCLS; c++) { lg[c] = __expf(lg[c] - mx); ssum += lg[c]; }
    float is = 1.0f / ssum;
#pragma unroll
    for (int c = 0; c < NCLS; c++) out[g * NCLS + c] = lg[c] * is;
}

// ---------------- launch ----------------
extern "C" void kernel_launch(void* const* d_in, const int* in_sizes, int n_in,
                              void* d_out, int out_size) {
    const float* x    = (const float*)d_in[0];
    const void*  ei   = d_in[1];
    const void*  bat  = d_in[2];
    const float* W    = (const float*)d_in[3];
    const float* asrc = (const float*)d_in[4];
    const float* adst = (const float*)d_in[5];
    const float* bias = (const float*)d_in[6];
    const float* lw   = (const float*)d_in[7];
    const float* lb   = (const float*)d_in[8];

    detect_kernel<<<1, 256>>>((const int*)ei);

    const int gemmBlocks     = (Nn + 127) / 128;
    const int nodeWarpBlocks = (Nn * 32 + 255) / 256;
    const int edgeBlocks     = (E2c + 255) / 256;
    const int scatBlocks     = (int)(((long long)E2c * 32 + 255) / 256);
    const int initBlocks     = (Nn * 128 + 255) / 256;

    for (int l = 0; l < 3; l++) {
        if (l == 0)
            gemm_kernel<0><<<gemmBlocks, 256>>>(x, W + l * 16384, nullptr);
        else
            gemm_kernel<1><<<gemmBlocks, 256>>>(nullptr, W + l * 16384,
                                                bias + (l - 1) * 128);
        init_layer_kernel<<<initBlocks, 256>>>();
        alpha_kernel<<<nodeWarpBlocks, 256>>>(asrc + l * 128, adst + l * 128);
        edge_max_kernel<<<edgeBlocks, 256>>>(ei);
        edge_exp_kernel<<<edgeBlocks, 256>>>(ei);
        scatter_kernel<<<scatBlocks, 256>>>(ei);
    }
    init_pool_kernel<<<(NG * 128 + 255) / 256, 256>>>();
    pool_kernel<<<nodeWarpBlocks, 256>>>(bat, bias + 2 * 128);
    head_kernel<<<1, 64>>>(lw, lb, (float*)d_out);
}

// round 7
// speedup vs baseline: 1.5254x; 1.5254x over previous
#include <cuda_runtime.h>
#include <math.h>

#define Nn   50000
#define Ee   800000
#define E2c  850000      // E + N self-loops
#define NG   64
#define NCLS 10

// ---------------- device scratch ----------------
__device__ float g_h[(size_t)Nn * 128];     // per-layer GEMM output  [N,128]
__device__ float g_out[(size_t)Nn * 128];   // per-layer aggregation  [N,128] (normalized)
__device__ float g_asrc[Nn * 2];            // alpha_src  [N,H]
__device__ float g_adst[Nn * 2];            // alpha_dst  [N,H]
__device__ int   g_deg[Nn];                 // degree counts
__device__ int   g_rowptr[Nn + 1];          // CSR row offsets
__device__ int   g_cursor[Nn];              // fill cursors
__device__ int   g_eidx[E2c];               // src node per CSR slot
__device__ float g_pool[NG * 128];
__device__ float g_cnt[NG];
__device__ int   g_is64;

// ---------------- helpers ----------------
__device__ __forceinline__ float eluf(float v) { return v > 0.f ? v : expm1f(v); }
__device__ __forceinline__ int loadIdx(const void* p, int i) {
    if (g_is64) return (int)((const long long*)p)[i];
    return ((const int*)p)[i];
}
__device__ __forceinline__ void red_add_v4(float* dst, float4 v) {
    asm volatile("red.global.add.v4.f32 [%0], {%1,%2,%3,%4};"
                 :: "l"(dst), "f"(v.x), "f"(v.y), "f"(v.z), "f"(v.w) : "memory");
}

// ---------------- dtype detection (int32 vs int64 edge indices) ----------------
__global__ void detect_kernel(const int* ei32) {
    __shared__ int sh;
    if (threadIdx.x == 0) sh = 0;
    __syncthreads();
    int v = 0;
    for (int i = threadIdx.x; i < 2048; i += 256) v |= ei32[2 * i + 1];
    atomicOr(&sh, v);
    __syncthreads();
    if (threadIdx.x == 0) g_is64 = (sh == 0) ? 1 : 0;
}

// ---------------- CSR build ----------------
__global__ void zero_deg_kernel() {
    int i = blockIdx.x * blockDim.x + threadIdx.x;
    if (i < Nn) g_deg[i] = 0;
}

__global__ void degree_kernel(const void* __restrict__ ei) {
    int e = blockIdx.x * blockDim.x + threadIdx.x;
    if (e >= E2c) return;
    int d = (e < Ee) ? loadIdx(ei, Ee + e) : (e - Ee);
    atomicAdd(&g_deg[d], 1);
}

__global__ void scan_kernel() {
    __shared__ int sh[1024];
    __shared__ int carry;
    int tid = threadIdx.x;
    if (tid == 0) carry = 0;
    __syncthreads();
    for (int chunk = 0; chunk < Nn; chunk += 1024) {
        int idx = chunk + tid;
        int v = (idx < Nn) ? g_deg[idx] : 0;
        sh[tid] = v;
        __syncthreads();
        for (int o = 1; o < 1024; o <<= 1) {
            int t = (tid >= o) ? sh[tid - o] : 0;
            __syncthreads();
            sh[tid] += t;
            __syncthreads();
        }
        int excl = carry + sh[tid] - v;
        if (idx < Nn) { g_rowptr[idx] = excl; g_cursor[idx] = excl; }
        __syncthreads();
        if (tid == 0) carry += sh[1023];
        __syncthreads();
    }
    if (tid == 0) g_rowptr[Nn] = carry;
}

__global__ void fill_kernel(const void* __restrict__ ei) {
    int e = blockIdx.x * blockDim.x + threadIdx.x;
    if (e >= E2c) return;
    int s, d;
    if (e < Ee) { s = loadIdx(ei, e); d = loadIdx(ei, Ee + e); }
    else        { s = e - Ee; d = s; }
    int pos = atomicAdd(&g_cursor[d], 1);
    g_eidx[pos] = s;
}

// ---------------- GEMM + fused alpha epilogue ----------------
// MODE 0: X = raw input. MODE 1: X = elu(g_out + biasPrev) (g_out pre-normalized)
template <int MODE>
__global__ void gemm_kernel(const float* __restrict__ X,
                            const float* __restrict__ Wm,
                            const float* __restrict__ biasPrev,
                            const float* __restrict__ attS,
                            const float* __restrict__ attD) {
    __shared__ float As[16][128];   // [k][m]
    __shared__ float Bs[16][128];   // [k][n]
    const int tid = threadIdx.x;
    const int bm  = blockIdx.x * 128;
    const int tx  = tid & 15;
    const int ty  = tid >> 4;
    float acc[8][8];
#pragma unroll
    for (int i = 0; i < 8; i++)
#pragma unroll
        for (int j = 0; j < 8; j++) acc[i][j] = 0.f;

    for (int k0 = 0; k0 < 128; k0 += 16) {
#pragma unroll
        for (int t = 0; t < 2; t++) {
            int e   = tid + t * 256;
            int row = e >> 2;
            int kk4 = (e & 3) << 2;
            int gr  = bm + row;
            float4 v = make_float4(0.f, 0.f, 0.f, 0.f);
            if (gr < Nn) {
                if (MODE == 0) {
                    v = *(const float4*)(X + (size_t)gr * 128 + k0 + kk4);
                } else {
                    v = *(const float4*)(g_out + (size_t)gr * 128 + k0 + kk4);
                    v.x = eluf(v.x + biasPrev[k0 + kk4 + 0]);
                    v.y = eluf(v.y + biasPrev[k0 + kk4 + 1]);
                    v.z = eluf(v.z + biasPrev[k0 + kk4 + 2]);
                    v.w = eluf(v.w + biasPrev[k0 + kk4 + 3]);
                }
            }
            As[kk4 + 0][row] = v.x;
            As[kk4 + 1][row] = v.y;
            As[kk4 + 2][row] = v.z;
            As[kk4 + 3][row] = v.w;
            int kb = e >> 5;
            int n4 = (e & 31) << 2;
            *(float4*)&Bs[kb][n4] = *(const float4*)(Wm + (size_t)(k0 + kb) * 128 + n4);
        }
        __syncthreads();
#pragma unroll
        for (int kk = 0; kk < 16; kk++) {
            float a[8], b[8];
            *(float4*)&a[0] = *(const float4*)&As[kk][ty * 8];
            *(float4*)&a[4] = *(const float4*)&As[kk][ty * 8 + 4];
            *(float4*)&b[0] = *(const float4*)&Bs[kk][tx * 8];
            *(float4*)&b[4] = *(const float4*)&Bs[kk][tx * 8 + 4];
#pragma unroll
            for (int i = 0; i < 8; i++)
#pragma unroll
                for (int j = 0; j < 8; j++)
                    acc[i][j] = fmaf(a[i], b[j], acc[i][j]);
        }
        __syncthreads();
    }

    // store h
#pragma unroll
    for (int i = 0; i < 8; i++) {
        int gr = bm + ty * 8 + i;
        if (gr < Nn) {
            *(float4*)(g_h + (size_t)gr * 128 + tx * 8) =
                make_float4(acc[i][0], acc[i][1], acc[i][2], acc[i][3]);
            *(float4*)(g_h + (size_t)gr * 128 + tx * 8 + 4) =
                make_float4(acc[i][4], acc[i][5], acc[i][6], acc[i][7]);
        }
    }

    // fused alpha: this thread's 8 cols (tx*8..tx*8+7) lie in one head (tx<8 -> head0)
    float as[8], ad[8];
    *(float4*)&as[0] = *(const float4*)(attS + tx * 8);
    *(float4*)&as[4] = *(const float4*)(attS + tx * 8 + 4);
    *(float4*)&ad[0] = *(const float4*)(attD + tx * 8);
    *(float4*)&ad[4] = *(const float4*)(attD + tx * 8 + 4);
    int head = tx >> 3;
#pragma unroll
    for (int i = 0; i < 8; i++) {
        float s = 0.f, d = 0.f;
#pragma unroll
        for (int j = 0; j < 8; j++) {
            s = fmaf(acc[i][j], as[j], s);
            d = fmaf(acc[i][j], ad[j], d);
        }
#pragma unroll
        for (int o = 4; o; o >>= 1) {
            s += __shfl_xor_sync(0xFFFFFFFFu, s, o);
            d += __shfl_xor_sync(0xFFFFFFFFu, d, o);
        }
        if ((tx & 7) == 0) {
            int gr = bm + ty * 8 + i;
            if (gr < Nn) {
                g_asrc[gr * 2 + head] = s;
                g_adst[gr * 2 + head] = d;
            }
        }
    }
}

// ---------------- fused edge softmax + aggregate (warp per dst node) ----------------
__global__ void aggregate_kernel() {
    int gid  = blockIdx.x * blockDim.x + threadIdx.x;
    int n    = gid >> 5;
    if (n >= Nn) return;
    int lane = gid & 31;
    int hh   = lane >> 4;

    float ad0 = g_adst[n * 2 + 0];
    float ad1 = g_adst[n * 2 + 1];
    int start = g_rowptr[n];
    int end   = g_rowptr[n + 1];

    float z0 = 0.f, z1 = 0.f;
    float4 accA = make_float4(0.f, 0.f, 0.f, 0.f);
    float4 accB = make_float4(0.f, 0.f, 0.f, 0.f);

    for (int base = start; base < end; base += 32) {
        int i = base + lane;
        int s = 0; float p0 = 0.f, p1 = 0.f;
        if (i < end) {
            s = g_eidx[i];
            float l0 = g_asrc[s * 2 + 0] + ad0; l0 = l0 > 0.f ? l0 : 0.2f * l0;
            float l1 = g_asrc[s * 2 + 1] + ad1; l1 = l1 > 0.f ? l1 : 0.2f * l1;
            p0 = __expf(l0); p1 = __expf(l1);
            z0 += p0; z1 += p1;
        }
        int cnt = min(32, end - base);
        int j = 0;
        for (; j + 1 < cnt; j += 2) {
            int   sA  = __shfl_sync(0xFFFFFFFFu, s, j);
            float pA0 = __shfl_sync(0xFFFFFFFFu, p0, j);
            float pA1 = __shfl_sync(0xFFFFFFFFu, p1, j);
            int   sB  = __shfl_sync(0xFFFFFFFFu, s, j + 1);
            float pB0 = __shfl_sync(0xFFFFFFFFu, p0, j + 1);
            float pB1 = __shfl_sync(0xFFFFFFFFu, p1, j + 1);
            float pA = hh ? pA1 : pA0;
            float pB = hh ? pB1 : pB0;
            float4 hA = *(const float4*)(g_h + (size_t)sA * 128 + lane * 4);
            float4 hB = *(const float4*)(g_h + (size_t)sB * 128 + lane * 4);
            accA.x = fmaf(pA, hA.x, accA.x); accA.y = fmaf(pA, hA.y, accA.y);
            accA.z = fmaf(pA, hA.z, accA.z); accA.w = fmaf(pA, hA.w, accA.w);
            accB.x = fmaf(pB, hB.x, accB.x); accB.y = fmaf(pB, hB.y, accB.y);
            accB.z = fmaf(pB, hB.z, accB.z); accB.w = fmaf(pB, hB.w, accB.w);
        }
        if (j < cnt) {
            int   sA  = __shfl_sync(0xFFFFFFFFu, s, j);
            float pA0 = __shfl_sync(0xFFFFFFFFu, p0, j);
            float pA1 = __shfl_sync(0xFFFFFFFFu, p1, j);
            float pA = hh ? pA1 : pA0;
            float4 hA = *(const float4*)(g_h + (size_t)sA * 128 + lane * 4);
            accA.x = fmaf(pA, hA.x, accA.x); accA.y = fmaf(pA, hA.y, accA.y);
            accA.z = fmaf(pA, hA.z, accA.z); accA.w = fmaf(pA, hA.w, accA.w);
        }
    }
#pragma unroll
    for (int o = 16; o; o >>= 1) {
        z0 += __shfl_xor_sync(0xFFFFFFFFu, z0, o);
        z1 += __shfl_xor_sync(0xFFFFFFFFu, z1, o);
    }
    float inv = 1.0f / (hh ? z1 : z0);
    float4 r;
    r.x = (accA.x + accB.x) * inv;
    r.y = (accA.y + accB.y) * inv;
    r.z = (accA.z + accB.z) * inv;
    r.w = (accA.w + accB.w) * inv;
    *(float4*)(g_out + (size_t)n * 128 + lane * 4) = r;
}

// ---------------- pooling ----------------
__global__ void init_pool_kernel() {
    int i = blockIdx.x * blockDim.x + threadIdx.x;
    if (i < NG * 128) g_pool[i] = 0.f;
    if (i < NG) g_cnt[i] = 0.f;
}

__global__ void pool_kernel(const void* __restrict__ batch,
                            const float* __restrict__ bias2) {
    int gid  = blockIdx.x * blockDim.x + threadIdx.x;
    int n    = gid >> 5;
    int lane = gid & 31;
    if (n >= Nn) return;
    int g = loadIdx(batch, n);
    float4 v = *(const float4*)(g_out + (size_t)n * 128 + lane * 4);
    const float* bp = bias2 + lane * 4;
    v.x = eluf(v.x + bp[0]);
    v.y = eluf(v.y + bp[1]);
    v.z = eluf(v.z + bp[2]);
    v.w = eluf(v.w + bp[3]);
    red_add_v4(g_pool + g * 128 + lane * 4, v);
    if (lane == 0) atomicAdd(&g_cnt[g], 1.0f);
}

// ---------------- classifier head + softmax ----------------
__global__ void head_kernel(const float* __restrict__ lw,
                            const float* __restrict__ lb,
                            float* __restrict__ out) {
    int g = threadIdx.x;
    if (g >= NG) return;
    float inv = 1.0f / fmaxf(g_cnt[g], 1.0f);
    float lg[NCLS];
#pragma unroll
    for (int c = 0; c < NCLS; c++) lg[c] = lb[c];
    for (int k = 0; k < 128; k++) {
        float pv = g_pool[g * 128 + k] * inv;
#pragma unroll
        for (int c = 0; c < NCLS; c++) lg[c] = fmaf(pv, lw[k * NCLS + c], lg[c]);
    }
    float mx = lg[0];
#pragma unroll
    for (int c = 1; c < NCLS; c++) mx = fmaxf(mx, lg[c]);
    float ssum = 0.f;
#pragma unroll
    for (int c = 0; c < NCLS; c++) { lg[c] = __expf(lg[c] - mx); ssum += lg[c]; }
    float is = 1.0f / ssum;
#pragma unroll
    for (int c = 0; c < NCLS; c++) out[g * NCLS + c] = lg[c] * is;
}

// ---------------- launch ----------------
extern "C" void kernel_launch(void* const* d_in, const int* in_sizes, int n_in,
                              void* d_out, int out_size) {
    const float* x    = (const float*)d_in[0];
    const void*  ei   = d_in[1];
    const void*  bat  = d_in[2];
    const float* W    = (const float*)d_in[3];
    const float* asrc = (const float*)d_in[4];
    const float* adst = (const float*)d_in[5];
    const float* bias = (const float*)d_in[6];
    const float* lw   = (const float*)d_in[7];
    const float* lb   = (const float*)d_in[8];

    const int gemmBlocks     = (Nn + 127) / 128;
    const int nodeWarpBlocks = (Nn * 32 + 255) / 256;
    const int edgeBlocks     = (E2c + 255) / 256;
    const int nodeBlocks     = (Nn + 255) / 256;

    detect_kernel<<<1, 256>>>((const int*)ei);

    // CSR build (once per launch)
    zero_deg_kernel<<<nodeBlocks, 256>>>();
    degree_kernel<<<edgeBlocks, 256>>>(ei);
    scan_kernel<<<1, 1024>>>();
    fill_kernel<<<edgeBlocks, 256>>>(ei);

    for (int l = 0; l < 3; l++) {
        if (l == 0)
            gemm_kernel<0><<<gemmBlocks, 256>>>(x, W, nullptr,
                                                asrc, adst);
        else
            gemm_kernel<1><<<gemmBlocks, 256>>>(nullptr, W + l * 16384,
                                                bias + (l - 1) * 128,
                                                asrc + l * 128, adst + l * 128);
        aggregate_kernel<<<nodeWarpBlocks, 256>>>();
    }
    init_pool_kernel<<<(NG * 128 + 255) / 256, 256>>>();
    pool_kernel<<<nodeWarpBlocks, 256>>>(bat, bias + 2 * 128);
    head_kernel<<<1, 64>>>(lw, lb, (float*)d_out);
}

// round 8
// speedup vs baseline: 1.5276x; 1.0015x over previous
#include <cuda_runtime.h>
#include <math.h>

#define Nn   50000
#define Ee   800000
#define E2c  850000      // E + N self-loops
#define NG   64
#define NCLS 10

// ---------------- device scratch ----------------
__device__ float g_h[(size_t)Nn * 128];     // per-layer GEMM output  [N,128]
__device__ float g_out[(size_t)Nn * 128];   // per-layer aggregation  [N,128] (normalized)
__device__ float g_asrc[Nn * 2];            // alpha_src  [N,H]
__device__ float g_adst[Nn * 2];            // alpha_dst  [N,H]
__device__ int   g_deg[Nn];                 // degree counts
__device__ int   g_rowptr[Nn + 1];          // CSR row offsets
__device__ int   g_cursor[Nn];              // fill cursors
__device__ int   g_eidx[E2c];               // src node per CSR slot
__device__ float g_pool[NG * 128];
__device__ float g_cnt[NG];
__device__ int   g_is64;

// ---------------- helpers ----------------
__device__ __forceinline__ float eluf(float v) { return v > 0.f ? v : expm1f(v); }
__device__ __forceinline__ int loadIdx(const void* p, int i) {
    if (g_is64) return (int)((const long long*)p)[i];
    return ((const int*)p)[i];
}
__device__ __forceinline__ void red_add_v4(float* dst, float4 v) {
    asm volatile("red.global.add.v4.f32 [%0], {%1,%2,%3,%4};"
                 :: "l"(dst), "f"(v.x), "f"(v.y), "f"(v.z), "f"(v.w) : "memory");
}

// ---------------- dtype detection (int32 vs int64 edge indices) ----------------
__global__ void detect_kernel(const int* ei32) {
    __shared__ int sh;
    if (threadIdx.x == 0) sh = 0;
    __syncthreads();
    int v = 0;
    for (int i = threadIdx.x; i < 2048; i += 256) v |= ei32[2 * i + 1];
    atomicOr(&sh, v);
    __syncthreads();
    if (threadIdx.x == 0) g_is64 = (sh == 0) ? 1 : 0;
}

// ---------------- CSR build ----------------
__global__ void zero_deg_kernel() {
    int i = blockIdx.x * blockDim.x + threadIdx.x;
    if (i < Nn) g_deg[i] = 0;
}

__global__ void degree_kernel(const void* __restrict__ ei) {
    int e = blockIdx.x * blockDim.x + threadIdx.x;
    if (e >= E2c) return;
    int d = (e < Ee) ? loadIdx(ei, Ee + e) : (e - Ee);
    atomicAdd(&g_deg[d], 1);
}

__global__ void scan_kernel() {
    __shared__ int sh[1024];
    __shared__ int carry;
    int tid = threadIdx.x;
    if (tid == 0) carry = 0;
    __syncthreads();
    for (int chunk = 0; chunk < Nn; chunk += 1024) {
        int idx = chunk + tid;
        int v = (idx < Nn) ? g_deg[idx] : 0;
        sh[tid] = v;
        __syncthreads();
        for (int o = 1; o < 1024; o <<= 1) {
            int t = (tid >= o) ? sh[tid - o] : 0;
            __syncthreads();
            sh[tid] += t;
            __syncthreads();
        }
        int excl = carry + sh[tid] - v;
        if (idx < Nn) { g_rowptr[idx] = excl; g_cursor[idx] = excl; }
        __syncthreads();
        if (tid == 0) carry += sh[1023];
        __syncthreads();
    }
    if (tid == 0) g_rowptr[Nn] = carry;
}

__global__ void fill_kernel(const void* __restrict__ ei) {
    int e = blockIdx.x * blockDim.x + threadIdx.x;
    if (e >= E2c) return;
    int s, d;
    if (e < Ee) { s = loadIdx(ei, e); d = loadIdx(ei, Ee + e); }
    else        { s = e - Ee; d = s; }
    int pos = atomicAdd(&g_cursor[d], 1);
    g_eidx[pos] = s;
}

// ---------------- GEMM + fused alpha epilogue ----------------
// MODE 0: X = raw input. MODE 1: X = elu(g_out + biasPrev) (g_out pre-normalized)
template <int MODE>
__global__ void gemm_kernel(const float* __restrict__ X,
                            const float* __restrict__ Wm,
                            const float* __restrict__ biasPrev,
                            const float* __restrict__ attS,
                            const float* __restrict__ attD) {
    __shared__ float As[16][128];   // [k][m]
    __shared__ float Bs[16][128];   // [k][n]
    const int tid = threadIdx.x;
    const int bm  = blockIdx.x * 128;
    const int tx  = tid & 15;
    const int ty  = tid >> 4;
    float acc[8][8];
#pragma unroll
    for (int i = 0; i < 8; i++)
#pragma unroll
        for (int j = 0; j < 8; j++) acc[i][j] = 0.f;

    for (int k0 = 0; k0 < 128; k0 += 16) {
#pragma unroll
        for (int t = 0; t < 2; t++) {
            int e   = tid + t * 256;
            int row = e >> 2;
            int kk4 = (e & 3) << 2;
            int gr  = bm + row;
            float4 v = make_float4(0.f, 0.f, 0.f, 0.f);
            if (gr < Nn) {
                if (MODE == 0) {
                    v = *(const float4*)(X + (size_t)gr * 128 + k0 + kk4);
                } else {
                    v = *(const float4*)(g_out + (size_t)gr * 128 + k0 + kk4);
                    v.x = eluf(v.x + biasPrev[k0 + kk4 + 0]);
                    v.y = eluf(v.y + biasPrev[k0 + kk4 + 1]);
                    v.z = eluf(v.z + biasPrev[k0 + kk4 + 2]);
                    v.w = eluf(v.w + biasPrev[k0 + kk4 + 3]);
                }
            }
            As[kk4 + 0][row] = v.x;
            As[kk4 + 1][row] = v.y;
            As[kk4 + 2][row] = v.z;
            As[kk4 + 3][row] = v.w;
            int kb = e >> 5;
            int n4 = (e & 31) << 2;
            *(float4*)&Bs[kb][n4] = *(const float4*)(Wm + (size_t)(k0 + kb) * 128 + n4);
        }
        __syncthreads();
#pragma unroll
        for (int kk = 0; kk < 16; kk++) {
            float a[8], b[8];
            *(float4*)&a[0] = *(const float4*)&As[kk][ty * 8];
            *(float4*)&a[4] = *(const float4*)&As[kk][ty * 8 + 4];
            *(float4*)&b[0] = *(const float4*)&Bs[kk][tx * 8];
            *(float4*)&b[4] = *(const float4*)&Bs[kk][tx * 8 + 4];
#pragma unroll
            for (int i = 0; i < 8; i++)
#pragma unroll
                for (int j = 0; j < 8; j++)
                    acc[i][j] = fmaf(a[i], b[j], acc[i][j]);
        }
        __syncthreads();
    }

    // store h
#pragma unroll
    for (int i = 0; i < 8; i++) {
        int gr = bm + ty * 8 + i;
        if (gr < Nn) {
            *(float4*)(g_h + (size_t)gr * 128 + tx * 8) =
                make_float4(acc[i][0], acc[i][1], acc[i][2], acc[i][3]);
            *(float4*)(g_h + (size_t)gr * 128 + tx * 8 + 4) =
                make_float4(acc[i][4], acc[i][5], acc[i][6], acc[i][7]);
        }
    }

    // fused alpha: this thread's 8 cols (tx*8..tx*8+7) lie in one head (tx<8 -> head0)
    float as[8], ad[8];
    *(float4*)&as[0] = *(const float4*)(attS + tx * 8);
    *(float4*)&as[4] = *(const float4*)(attS + tx * 8 + 4);
    *(float4*)&ad[0] = *(const float4*)(attD + tx * 8);
    *(float4*)&ad[4] = *(const float4*)(attD + tx * 8 + 4);
    int head = tx >> 3;
#pragma unroll
    for (int i = 0; i < 8; i++) {
        float s = 0.f, d = 0.f;
#pragma unroll
        for (int j = 0; j < 8; j++) {
            s = fmaf(acc[i][j], as[j], s);
            d = fmaf(acc[i][j], ad[j], d);
        }
#pragma unroll
        for (int o = 4; o; o >>= 1) {
            s += __shfl_xor_sync(0xFFFFFFFFu, s, o);
            d += __shfl_xor_sync(0xFFFFFFFFu, d, o);
        }
        if ((tx & 7) == 0) {
            int gr = bm + ty * 8 + i;
            if (gr < Nn) {
                g_asrc[gr * 2 + head] = s;
                g_adst[gr * 2 + head] = d;
            }
        }
    }
}

// ---------------- fused edge softmax + aggregate (warp per dst node) ----------------
__global__ void aggregate_kernel() {
    int gid  = blockIdx.x * blockDim.x + threadIdx.x;
    int n    = gid >> 5;
    if (n >= Nn) return;
    int lane = gid & 31;
    int hh   = lane >> 4;

    float ad0 = g_adst[n * 2 + 0];
    float ad1 = g_adst[n * 2 + 1];
    int start = g_rowptr[n];
    int end   = g_rowptr[n + 1];

    float z0 = 0.f, z1 = 0.f;
    float4 accA = make_float4(0.f, 0.f, 0.f, 0.f);
    float4 accB = make_float4(0.f, 0.f, 0.f, 0.f);

    for (int base = start; base < end; base += 32) {
        int i = base + lane;
        int s = 0; float p0 = 0.f, p1 = 0.f;
        if (i < end) {
            s = g_eidx[i];
            float l0 = g_asrc[s * 2 + 0] + ad0; l0 = l0 > 0.f ? l0 : 0.2f * l0;
            float l1 = g_asrc[s * 2 + 1] + ad1; l1 = l1 > 0.f ? l1 : 0.2f * l1;
            p0 = __expf(l0); p1 = __expf(l1);
            z0 += p0; z1 += p1;
        }
        int cnt = min(32, end - base);
        int j = 0;
        for (; j + 1 < cnt; j += 2) {
            int   sA  = __shfl_sync(0xFFFFFFFFu, s, j);
            float pA0 = __shfl_sync(0xFFFFFFFFu, p0, j);
            float pA1 = __shfl_sync(0xFFFFFFFFu, p1, j);
            int   sB  = __shfl_sync(0xFFFFFFFFu, s, j + 1);
            float pB0 = __shfl_sync(0xFFFFFFFFu, p0, j + 1);
            float pB1 = __shfl_sync(0xFFFFFFFFu, p1, j + 1);
            float pA = hh ? pA1 : pA0;
            float pB = hh ? pB1 : pB0;
            float4 hA = *(const float4*)(g_h + (size_t)sA * 128 + lane * 4);
            float4 hB = *(const float4*)(g_h + (size_t)sB * 128 + lane * 4);
            accA.x = fmaf(pA, hA.x, accA.x); accA.y = fmaf(pA, hA.y, accA.y);
            accA.z = fmaf(pA, hA.z, accA.z); accA.w = fmaf(pA, hA.w, accA.w);
            accB.x = fmaf(pB, hB.x, accB.x); accB.y = fmaf(pB, hB.y, accB.y);
            accB.z = fmaf(pB, hB.z, accB.z); accB.w = fmaf(pB, hB.w, accB.w);
        }
        if (j < cnt) {
            int   sA  = __shfl_sync(0xFFFFFFFFu, s, j);
            float pA0 = __shfl_sync(0xFFFFFFFFu, p0, j);
            float pA1 = __shfl_sync(0xFFFFFFFFu, p1, j);
            float pA = hh ? pA1 : pA0;
            float4 hA = *(const float4*)(g_h + (size_t)sA * 128 + lane * 4);
            accA.x = fmaf(pA, hA.x, accA.x); accA.y = fmaf(pA, hA.y, accA.y);
            accA.z = fmaf(pA, hA.z, accA.z); accA.w = fmaf(pA, hA.w, accA.w);
        }
    }
#pragma unroll
    for (int o = 16; o; o >>= 1) {
        z0 += __shfl_xor_sync(0xFFFFFFFFu, z0, o);
        z1 += __shfl_xor_sync(0xFFFFFFFFu, z1, o);
    }
    float inv = 1.0f / (hh ? z1 : z0);
    float4 r;
    r.x = (accA.x + accB.x) * inv;
    r.y = (accA.y + accB.y) * inv;
    r.z = (accA.z + accB.z) * inv;
    r.w = (accA.w + accB.w) * inv;
    *(float4*)(g_out + (size_t)n * 128 + lane * 4) = r;
}

// ---------------- pooling ----------------
__global__ void init_pool_kernel() {
    int i = blockIdx.x * blockDim.x + threadIdx.x;
    if (i < NG * 128) g_pool[i] = 0.f;
    if (i < NG) g_cnt[i] = 0.f;
}

__global__ void pool_kernel(const void* __restrict__ batch,
                            const float* __restrict__ bias2) {
    int gid  = blockIdx.x * blockDim.x + threadIdx.x;
    int n    = gid >> 5;
    int lane = gid & 31;
    if (n >= Nn) return;
    int g = loadIdx(batch, n);
    float4 v = *(const float4*)(g_out + (size_t)n * 128 + lane * 4);
    const float* bp = bias2 + lane * 4;
    v.x = eluf(v.x + bp[0]);
    v.y = eluf(v.y + bp[1]);
    v.z = eluf(v.z + bp[2]);
    v.w = eluf(v.w + bp[3]);
    red_add_v4(g_pool + g * 128 + lane * 4, v);
    if (lane == 0) atomicAdd(&g_cnt[g], 1.0f);
}

// ---------------- classifier head + softmax ----------------
__global__ void head_kernel(const float* __restrict__ lw,
                            const float* __restrict__ lb,
                            float* __restrict__ out) {
    int g = threadIdx.x;
    if (g >= NG) return;
    float inv = 1.0f / fmaxf(g_cnt[g], 1.0f);
    float lg[NCLS];
#pragma unroll
    for (int c = 0; c < NCLS; c++) lg[c] = lb[c];
    for (int k = 0; k < 128; k++) {
        float pv = g_pool[g * 128 + k] * inv;
#pragma unroll
        for (int c = 0; c < NCLS; c++) lg[c] = fmaf(pv, lw[k * NCLS + c], lg[c]);
    }
    float mx = lg[0];
#pragma unroll
    for (int c = 1; c < NCLS; c++) mx = fmaxf(mx, lg[c]);
    float ssum = 0.f;
#pragma unroll
    for (int c = 0; c < NCLS; c++) { lg[c] = __expf(lg[c] - mx); ssum += lg[c]; }
    float is = 1.0f / ssum;
#pragma unroll
    for (int c = 0; c < NCLS; c++) out[g * NCLS + c] = lg[c] * is;
}

// ---------------- launch ----------------
extern "C" void kernel_launch(void* const* d_in, const int* in_sizes, int n_in,
                              void* d_out, int out_size) {
    const float* x    = (const float*)d_in[0];
    const void*  ei   = d_in[1];
    const void*  bat  = d_in[2];
    const float* W    = (const float*)d_in[3];
    const float* asrc = (const float*)d_in[4];
    const float* adst = (const float*)d_in[5];
    const float* bias = (const float*)d_in[6];
    const float* lw   = (const float*)d_in[7];
    const float* lb   = (const float*)d_in[8];

    const int gemmBlocks     = (Nn + 127) / 128;
    const int nodeWarpBlocks = (Nn * 32 + 255) / 256;
    const int edgeBlocks     = (E2c + 255) / 256;
    const int nodeBlocks     = (Nn + 255) / 256;

    detect_kernel<<<1, 256>>>((const int*)ei);

    // CSR build (once per launch)
    zero_deg_kernel<<<nodeBlocks, 256>>>();
    degree_kernel<<<edgeBlocks, 256>>>(ei);
    scan_kernel<<<1, 1024>>>();
    fill_kernel<<<edgeBlocks, 256>>>(ei);

    for (int l = 0; l < 3; l++) {
        if (l == 0)
            gemm_kernel<0><<<gemmBlocks, 256>>>(x, W, nullptr,
                                                asrc, adst);
        else
            gemm_kernel<1><<<gemmBlocks, 256>>>(nullptr, W + l * 16384,
                                                bias + (l - 1) * 128,
                                                asrc + l * 128, adst + l * 128);
        aggregate_kernel<<<nodeWarpBlocks, 256>>>();
    }
    init_pool_kernel<<<(NG * 128 + 255) / 256, 256>>>();
    pool_kernel<<<nodeWarpBlocks, 256>>>(bat, bias + 2 * 128);
    head_kernel<<<1, 64>>>(lw, lb, (float*)d_out);
}

// round 9
// speedup vs baseline: 1.5354x; 1.0051x over previous
#include <cuda_runtime.h>
#include <math.h>

#define Nn   50000
#define Ee   800000
#define E2c  850000      // E + N self-loops
#define NG   64
#define NCLS 10

// ---------------- device scratch ----------------
__device__ float g_h[(size_t)Nn * 128];     // per-layer GEMM output  [N,128]
__device__ float g_out[(size_t)Nn * 128];   // per-layer aggregation  [N,128] (normalized)
__device__ float g_asrc[Nn * 2];            // alpha_src  [N,H]
__device__ float g_adst[Nn * 2];            // alpha_dst  [N,H]
__device__ int   g_deg[Nn];                 // degree counts
__device__ int   g_rowptr[Nn + 1];          // CSR row offsets
__device__ int   g_cursor[Nn];              // fill cursors
__device__ int   g_eidx[E2c];               // src node per CSR slot
__device__ float g_pool[NG * 128];
__device__ float g_cnt[NG];
__device__ int   g_is64;

// ---------------- helpers ----------------
__device__ __forceinline__ float eluf(float v) { return v > 0.f ? v : expm1f(v); }
__device__ __forceinline__ int loadIdx(const void* p, int i) {
    if (g_is64) return (int)((const long long*)p)[i];
    return ((const int*)p)[i];
}
__device__ __forceinline__ void red_add_v4(float* dst, float4 v) {
    asm volatile("red.global.add.v4.f32 [%0], {%1,%2,%3,%4};"
                 :: "l"(dst), "f"(v.x), "f"(v.y), "f"(v.z), "f"(v.w) : "memory");
}

// ---------------- dtype detection (int32 vs int64 edge indices) ----------------
__global__ void detect_kernel(const int* ei32) {
    __shared__ int sh;
    if (threadIdx.x == 0) sh = 0;
    __syncthreads();
    int v = 0;
    for (int i = threadIdx.x; i < 2048; i += 256) v |= ei32[2 * i + 1];
    atomicOr(&sh, v);
    __syncthreads();
    if (threadIdx.x == 0) g_is64 = (sh == 0) ? 1 : 0;
}

// ---------------- CSR build ----------------
__global__ void zero_deg_kernel() {
    int i = blockIdx.x * blockDim.x + threadIdx.x;
    if (i < Nn) g_deg[i] = 0;
}

__global__ void degree_kernel(const void* __restrict__ ei) {
    int e = blockIdx.x * blockDim.x + threadIdx.x;
    if (e >= E2c) return;
    int d = (e < Ee) ? loadIdx(ei, Ee + e) : (e - Ee);
    atomicAdd(&g_deg[d], 1);
}

__global__ void scan_kernel() {
    __shared__ int sh[1024];
    __shared__ int carry;
    int tid = threadIdx.x;
    if (tid == 0) carry = 0;
    __syncthreads();
    for (int chunk = 0; chunk < Nn; chunk += 1024) {
        int idx = chunk + tid;
        int v = (idx < Nn) ? g_deg[idx] : 0;
        sh[tid] = v;
        __syncthreads();
        for (int o = 1; o < 1024; o <<= 1) {
            int t = (tid >= o) ? sh[tid - o] : 0;
            __syncthreads();
            sh[tid] += t;
            __syncthreads();
        }
        int excl = carry + sh[tid] - v;
        if (idx < Nn) { g_rowptr[idx] = excl; g_cursor[idx] = excl; }
        __syncthreads();
        if (tid == 0) carry += sh[1023];
        __syncthreads();
    }
    if (tid == 0) g_rowptr[Nn] = carry;
}

__global__ void fill_kernel(const void* __restrict__ ei) {
    int e = blockIdx.x * blockDim.x + threadIdx.x;
    if (e >= E2c) return;
    int s, d;
    if (e < Ee) { s = loadIdx(ei, e); d = loadIdx(ei, Ee + e); }
    else        { s = e - Ee; d = s; }
    int pos = atomicAdd(&g_cursor[d], 1);
    g_eidx[pos] = s;
}

// ---------------- GEMM + fused alpha epilogue ----------------
// MODE 0: X = raw input. MODE 1: X = elu(g_out + biasPrev) (g_out pre-normalized)
template <int MODE>
__global__ void gemm_kernel(const float* __restrict__ X,
                            const float* __restrict__ Wm,
                            const float* __restrict__ biasPrev,
                            const float* __restrict__ attS,
                            const float* __restrict__ attD) {
    __shared__ float As[16][128];   // [k][m]
    __shared__ float Bs[16][128];   // [k][n]
    const int tid = threadIdx.x;
    const int bm  = blockIdx.x * 128;
    const int tx  = tid & 15;
    const int ty  = tid >> 4;
    float acc[8][8];
#pragma unroll
    for (int i = 0; i < 8; i++)
#pragma unroll
        for (int j = 0; j < 8; j++) acc[i][j] = 0.f;

    for (int k0 = 0; k0 < 128; k0 += 16) {
#pragma unroll
        for (int t = 0; t < 2; t++) {
            int e   = tid + t * 256;
            int row = e >> 2;
            int kk4 = (e & 3) << 2;
            int gr  = bm + row;
            float4 v = make_float4(0.f, 0.f, 0.f, 0.f);
            if (gr < Nn) {
                if (MODE == 0) {
                    v = *(const float4*)(X + (size_t)gr * 128 + k0 + kk4);
                } else {
                    v = *(const float4*)(g_out + (size_t)gr * 128 + k0 + kk4);
                    v.x = eluf(v.x + biasPrev[k0 + kk4 + 0]);
                    v.y = eluf(v.y + biasPrev[k0 + kk4 + 1]);
                    v.z = eluf(v.z + biasPrev[k0 + kk4 + 2]);
                    v.w = eluf(v.w + biasPrev[k0 + kk4 + 3]);
                }
            }
            As[kk4 + 0][row] = v.x;
            As[kk4 + 1][row] = v.y;
            As[kk4 + 2][row] = v.z;
            As[kk4 + 3][row] = v.w;
            int kb = e >> 5;
            int n4 = (e & 31) << 2;
            *(float4*)&Bs[kb][n4] = *(const float4*)(Wm + (size_t)(k0 + kb) * 128 + n4);
        }
        __syncthreads();
#pragma unroll
        for (int kk = 0; kk < 16; kk++) {
            float a[8], b[8];
            *(float4*)&a[0] = *(const float4*)&As[kk][ty * 8];
            *(float4*)&a[4] = *(const float4*)&As[kk][ty * 8 + 4];
            *(float4*)&b[0] = *(const float4*)&Bs[kk][tx * 8];
            *(float4*)&b[4] = *(const float4*)&Bs[kk][tx * 8 + 4];
#pragma unroll
            for (int i = 0; i < 8; i++)
#pragma unroll
                for (int j = 0; j < 8; j++)
                    acc[i][j] = fmaf(a[i], b[j], acc[i][j]);
        }
        __syncthreads();
    }

    // store h
#pragma unroll
    for (int i = 0; i < 8; i++) {
        int gr = bm + ty * 8 + i;
        if (gr < Nn) {
            *(float4*)(g_h + (size_t)gr * 128 + tx * 8) =
                make_float4(acc[i][0], acc[i][1], acc[i][2], acc[i][3]);
            *(float4*)(g_h + (size_t)gr * 128 + tx * 8 + 4) =
                make_float4(acc[i][4], acc[i][5], acc[i][6], acc[i][7]);
        }
    }

    // fused alpha: this thread's 8 cols (tx*8..tx*8+7) lie in one head (tx<8 -> head0)
    float as[8], ad[8];
    *(float4*)&as[0] = *(const float4*)(attS + tx * 8);
    *(float4*)&as[4] = *(const float4*)(attS + tx * 8 + 4);
    *(float4*)&ad[0] = *(const float4*)(attD + tx * 8);
    *(float4*)&ad[4] = *(const float4*)(attD + tx * 8 + 4);
    int head = tx >> 3;
#pragma unroll
    for (int i = 0; i < 8; i++) {
        float s = 0.f, d = 0.f;
#pragma unroll
        for (int j = 0; j < 8; j++) {
            s = fmaf(acc[i][j], as[j], s);
            d = fmaf(acc[i][j], ad[j], d);
        }
#pragma unroll
        for (int o = 4; o; o >>= 1) {
            s += __shfl_xor_sync(0xFFFFFFFFu, s, o);
            d += __shfl_xor_sync(0xFFFFFFFFu, d, o);
        }
        if ((tx & 7) == 0) {
            int gr = bm + ty * 8 + i;
            if (gr < Nn) {
                g_asrc[gr * 2 + head] = s;
                g_adst[gr * 2 + head] = d;
            }
        }
    }
}

// ---------------- fused edge softmax + aggregate (warp per dst node) ----------------
__global__ void aggregate_kernel() {
    int gid  = blockIdx.x * blockDim.x + threadIdx.x;
    int n    = gid >> 5;
    if (n >= Nn) return;
    int lane = gid & 31;
    int hh   = lane >> 4;

    float ad0 = g_adst[n * 2 + 0];
    float ad1 = g_adst[n * 2 + 1];
    int start = g_rowptr[n];
    int end   = g_rowptr[n + 1];

    float z0 = 0.f, z1 = 0.f;
    float4 accA = make_float4(0.f, 0.f, 0.f, 0.f);
    float4 accB = make_float4(0.f, 0.f, 0.f, 0.f);

    for (int base = start; base < end; base += 32) {
        int i = base + lane;
        int s = 0; float p0 = 0.f, p1 = 0.f;
        if (i < end) {
            s = g_eidx[i];
            float l0 = g_asrc[s * 2 + 0] + ad0; l0 = l0 > 0.f ? l0 : 0.2f * l0;
            float l1 = g_asrc[s * 2 + 1] + ad1; l1 = l1 > 0.f ? l1 : 0.2f * l1;
            p0 = __expf(l0); p1 = __expf(l1);
            z0 += p0; z1 += p1;
        }
        int cnt = min(32, end - base);
        int j = 0;
        for (; j + 1 < cnt; j += 2) {
            int   sA  = __shfl_sync(0xFFFFFFFFu, s, j);
            float pA0 = __shfl_sync(0xFFFFFFFFu, p0, j);
            float pA1 = __shfl_sync(0xFFFFFFFFu, p1, j);
            int   sB  = __shfl_sync(0xFFFFFFFFu, s, j + 1);
            float pB0 = __shfl_sync(0xFFFFFFFFu, p0, j + 1);
            float pB1 = __shfl_sync(0xFFFFFFFFu, p1, j + 1);
            float pA = hh ? pA1 : pA0;
            float pB = hh ? pB1 : pB0;
            float4 hA = *(const float4*)(g_h + (size_t)sA * 128 + lane * 4);
            float4 hB = *(const float4*)(g_h + (size_t)sB * 128 + lane * 4);
            accA.x = fmaf(pA, hA.x, accA.x); accA.y = fmaf(pA, hA.y, accA.y);
            accA.z = fmaf(pA, hA.z, accA.z); accA.w = fmaf(pA, hA.w, accA.w);
            accB.x = fmaf(pB, hB.x, accB.x); accB.y = fmaf(pB, hB.y, accB.y);
            accB.z = fmaf(pB, hB.z, accB.z); accB.w = fmaf(pB, hB.w, accB.w);
        }
        if (j < cnt) {
            int   sA  = __shfl_sync(0xFFFFFFFFu, s, j);
            float pA0 = __shfl_sync(0xFFFFFFFFu, p0, j);
            float pA1 = __shfl_sync(0xFFFFFFFFu, p1, j);
            float pA = hh ? pA1 : pA0;
            float4 hA = *(const float4*)(g_h + (size_t)sA * 128 + lane * 4);
            accA.x = fmaf(pA, hA.x, accA.x); accA.y = fmaf(pA, hA.y, accA.y);
            accA.z = fmaf(pA, hA.z, accA.z); accA.w = fmaf(pA, hA.w, accA.w);
        }
    }
#pragma unroll
    for (int o = 16; o; o >>= 1) {
        z0 += __shfl_xor_sync(0xFFFFFFFFu, z0, o);
        z1 += __shfl_xor_sync(0xFFFFFFFFu, z1, o);
    }
    float inv = 1.0f / (hh ? z1 : z0);
    float4 r;
    r.x = (accA.x + accB.x) * inv;
    r.y = (accA.y + accB.y) * inv;
    r.z = (accA.z + accB.z) * inv;
    r.w = (accA.w + accB.w) * inv;
    *(float4*)(g_out + (size_t)n * 128 + lane * 4) = r;
}

// ---------------- pooling ----------------
__global__ void init_pool_kernel() {
    int i = blockIdx.x * blockDim.x + threadIdx.x;
    if (i < NG * 128) g_pool[i] = 0.f;
    if (i < NG) g_cnt[i] = 0.f;
}

__global__ void pool_kernel(const void* __restrict__ batch,
                            const float* __restrict__ bias2) {
    int gid  = blockIdx.x * blockDim.x + threadIdx.x;
    int n    = gid >> 5;
    int lane = gid & 31;
    if (n >= Nn) return;
    int g = loadIdx(batch, n);
    float4 v = *(const float4*)(g_out + (size_t)n * 128 + lane * 4);
    const float* bp = bias2 + lane * 4;
    v.x = eluf(v.x + bp[0]);
    v.y = eluf(v.y + bp[1]);
    v.z = eluf(v.z + bp[2]);
    v.w = eluf(v.w + bp[3]);
    red_add_v4(g_pool + g * 128 + lane * 4, v);
    if (lane == 0) atomicAdd(&g_cnt[g], 1.0f);
}

// ---------------- classifier head + softmax ----------------
__global__ void head_kernel(const float* __restrict__ lw,
                            const float* __restrict__ lb,
                            float* __restrict__ out) {
    int g = threadIdx.x;
    if (g >= NG) return;
    float inv = 1.0f / fmaxf(g_cnt[g], 1.0f);
    float lg[NCLS];
#pragma unroll
    for (int c = 0; c < NCLS; c++) lg[c] = lb[c];
    for (int k = 0; k < 128; k++) {
        float pv = g_pool[g * 128 + k] * inv;
#pragma unroll
        for (int c = 0; c < NCLS; c++) lg[c] = fmaf(pv, lw[k * NCLS + c], lg[c]);
    }
    float mx = lg[0];
#pragma unroll
    for (int c = 1; c < NCLS; c++) mx = fmaxf(mx, lg[c]);
    float ssum = 0.f;
#pragma unroll
    for (int c = 0; c < NCLS; c++) { lg[c] = __expf(lg[c] - mx); ssum += lg[c]; }
    float is = 1.0f / ssum;
#pragma unroll
    for (int c = 0; c < NCLS; c++) out[g * NCLS + c] = lg[c] * is;
}

// ---------------- launch ----------------
extern "C" void kernel_launch(void* const* d_in, const int* in_sizes, int n_in,
                              void* d_out, int out_size) {
    const float* x    = (const float*)d_in[0];
    const void*  ei   = d_in[1];
    const void*  bat  = d_in[2];
    const float* W    = (const float*)d_in[3];
    const float* asrc = (const float*)d_in[4];
    const float* adst = (const float*)d_in[5];
    const float* bias = (const float*)d_in[6];
    const float* lw   = (const float*)d_in[7];
    const float* lb   = (const float*)d_in[8];

    const int gemmBlocks     = (Nn + 127) / 128;
    const int nodeWarpBlocks = (Nn * 32 + 255) / 256;
    const int edgeBlocks     = (E2c + 255) / 256;
    const int nodeBlocks     = (Nn + 255) / 256;

    detect_kernel<<<1, 256>>>((const int*)ei);

    // CSR build (once per launch)
    zero_deg_kernel<<<nodeBlocks, 256>>>();
    degree_kernel<<<edgeBlocks, 256>>>(ei);
    scan_kernel<<<1, 1024>>>();
    fill_kernel<<<edgeBlocks, 256>>>(ei);

    for (int l = 0; l < 3; l++) {
        if (l == 0)
            gemm_kernel<0><<<gemmBlocks, 256>>>(x, W, nullptr,
                                                asrc, adst);
        else
            gemm_kernel<1><<<gemmBlocks, 256>>>(nullptr, W + l * 16384,
                                                bias + (l - 1) * 128,
                                                asrc + l * 128, adst + l * 128);
        aggregate_kernel<<<nodeWarpBlocks, 256>>>();
    }
    init_pool_kernel<<<(NG * 128 + 255) / 256, 256>>>();
    pool_kernel<<<nodeWarpBlocks, 256>>>(bat, bias + 2 * 128);
    head_kernel<<<1, 64>>>(lw, lb, (float*)d_out);
}